// round 14
// baseline (speedup 1.0000x reference)
#include <cuda_runtime.h>
#include <cuda_fp16.h>
#include <mma.h>
using namespace nvcuda;

#define Bn 8
#define Sn 2048
#define Dn 64
#define Hn 128
#define Tn 2047                   // S-1 sequential steps
#define BT (Bn*Tn)                // 16376 (b,t) rows
#define HH (Hn*Hn)                // 16384
#define NW 16512                  // HH + 128 (A columns + Bs columns)
#define Kd 65                     // D+1
#define KP 72                     // half pitch for GEMM tiles
#define SP 68                     // float pitch for GEMM epilogue staging
#define MB 64                     // GEMM m-tile (64 rows, 128-thread CTAs)
#define CC 36                     // chunks per batch chain
#define LL 57                     // steps per chunk (35*57=1995, last=52)
#define NCHUNK (Bn*CC)            // 288 chunk CTAs
#define AP 136                    // half pitch for phase-1 A/R tiles

// ---------------- scratch (device globals: allocation-free rule) ----------------
__device__ __align__(128) __half g_A[(size_t)BT * HH];     // 536.6 MB, A[bt][j*128+i] = A_t[i][j]
__device__ __align__(128) __half g_WaPh[NW * 64];          // permuted Wa cols 1..64 (+ Wb rows), fp16
__device__ __align__(128) __half g_Xh[Bn * Sn * Dn];       // X * dt, fp16
__device__ __align__(128) __half g_Q[(size_t)NCHUNK * HH]; // chunk transition Q = Phi - I, [j*128+i]
__device__ float g_A0[NW];                                  // dt * W[:,0] constant column term
__device__ float g_Bs[(size_t)BT * Hn];                     // per-step bias
__device__ float g_v[NCHUNK * Hn];                          // chunk bias accumulation
__device__ float g_ystart[NCHUNK * Hn];                     // chunk-start states
__device__ float g_y0[Bn * Hn];

// ---------------- helpers ----------------
__device__ __forceinline__ void cp_async16(void* d, const void* s) {
    unsigned ds = (unsigned)__cvta_generic_to_shared(d);
    asm volatile("cp.async.cg.shared.global [%0], [%1], 16;\n" :: "r"(ds), "l"(s));
}
__device__ __forceinline__ void ldsm4t(unsigned& r0, unsigned& r1, unsigned& r2, unsigned& r3, unsigned addr) {
    asm volatile("ldmatrix.sync.aligned.m8n8.x4.trans.shared.b16 {%0,%1,%2,%3}, [%4];\n"
        : "=r"(r0), "=r"(r1), "=r"(r2), "=r"(r3) : "r"(addr));
}
__device__ __forceinline__ void mma16816(float* c, unsigned a0, unsigned a1, unsigned a2, unsigned a3,
                                         unsigned b0, unsigned b1) {
    asm volatile("mma.sync.aligned.m16n8k16.row.col.f32.f16.f16.f32 "
        "{%0,%1,%2,%3}, {%4,%5,%6,%7}, {%8,%9}, {%0,%1,%2,%3};\n"
        : "+f"(c[0]), "+f"(c[1]), "+f"(c[2]), "+f"(c[3])
        : "r"(a0), "r"(a1), "r"(a2), "r"(a3), "r"(b0), "r"(b1));
}

// ---------------- kernel 0a: permute Wa (+append Wb) -> fp16, plus constant column term ----------------
__global__ void wap2_kernel(const float* __restrict__ Wa, const float* __restrict__ Wb) {
    int idx = blockIdx.x * 256 + threadIdx.x;
    const float dt = (float)(1.0 / 2047.0);
    if (idx < NW * 64) {
        int c = idx >> 6, k = idx & 63;
        if (c < HH) {
            int r = (c & 127) * Hn + (c >> 7);
            g_WaPh[idx] = __float2half(Wa[r * Kd + k + 1]);
            if (k == 0) g_A0[c] = dt * Wa[r * Kd];
        } else {
            int i = c - HH;
            g_WaPh[idx] = __float2half(Wb[i * Kd + k + 1]);
            if (k == 0) g_A0[c] = dt * Wb[i * Kd];
        }
    }
}

// ---------------- kernel 0b: X*dt -> fp16 ----------------
__global__ void xh_kernel(const float* __restrict__ X) {
    int i = blockIdx.x * 256 + threadIdx.x;
    const float dt = (float)(1.0 / 2047.0);
    if (i < Bn * Sn * Dn) g_Xh[i] = __float2half(X[i] * dt);
}

// ---------------- kernel 1: y0 = X[:,0] @ Wi.T + bi ----------------
__global__ void y0_kernel(const float* __restrict__ X, const float* __restrict__ Wi,
                          const float* __restrict__ bi, float* __restrict__ Y) {
    __shared__ float xs[Dn];
    int b = blockIdx.x, i = threadIdx.x;
    if (i < Dn) xs[i] = X[(size_t)b * Sn * Dn + i];
    __syncthreads();
    float acc = bi[i];
#pragma unroll
    for (int d = 0; d < Dn; ++d) acc += xs[d] * Wi[i * Dn + d];
    g_y0[b * Hn + i] = acc;
    Y[(size_t)b * Sn * Hn + i] = acc;   // ys[:,0]
}

// ---------------- kernel 3: A-GEMM, 64x128 tiles, 128 threads, 4 CTAs/SM, fused Bs n-tile ----------------
__global__ void __launch_bounds__(128, 4) a_gemm_wmma() {
    extern __shared__ char smraw[];
    __half* inpS = (__half*)smraw;                 // [64][KP]   (load phase)
    __half* waS  = inpS + MB * KP;                 // [128][KP]  (load phase)
    float*  stage = (float*)smraw;                 // reused after MMA: 4 warps x [32][SP]
    float*  A0s = (float*)(smraw + 4 * 32 * SP * 4);

    int tid = threadIdx.x, wid = tid >> 5, lane = tid & 31;
    int m0 = blockIdx.y * MB, n0 = blockIdx.x * 128;
    bool is_bs = (n0 >= HH);

    if (tid < Hn) A0s[tid] = g_A0[n0 + tid];

    for (int idx = tid; idx < MB * 8; idx += 128) {
        int r = idx >> 3, ch = idx & 7;
        int m = m0 + r;
        if (m < BT) {
            int b = m / Tn, t = m - b * Tn + 1;
            cp_async16(inpS + r * KP + ch * 8, g_Xh + ((size_t)(b * Sn + t)) * Dn + ch * 8);
        } else {
            *(uint4*)(inpS + r * KP + ch * 8) = make_uint4(0, 0, 0, 0);
        }
    }
    for (int idx = tid; idx < 128 * 8; idx += 128) {
        int r = idx >> 3, ch = idx & 7;
        cp_async16(waS + r * KP + ch * 8, g_WaPh + (size_t)(n0 + r) * 64 + ch * 8);
    }
    asm volatile("cp.async.commit_group;\ncp.async.wait_group 0;\n");
    __syncthreads();

    int wm = wid >> 1, wn = wid & 1;               // 2x2 warps, warp tile 32(M) x 64(N)
    wmma::fragment<wmma::accumulator, 16, 16, 16, float> acc[2][4];
#pragma unroll
    for (int i = 0; i < 2; ++i)
#pragma unroll
        for (int j = 0; j < 4; ++j) wmma::fill_fragment(acc[i][j], 0.f);

#pragma unroll
    for (int k4 = 0; k4 < 4; ++k4) {
        wmma::fragment<wmma::matrix_a, 16, 16, 16, __half, wmma::row_major> af[2];
        wmma::load_matrix_sync(af[0], inpS + (wm * 32) * KP + k4 * 16, KP);
        wmma::load_matrix_sync(af[1], inpS + (wm * 32 + 16) * KP + k4 * 16, KP);
#pragma unroll
        for (int ni = 0; ni < 4; ++ni) {
            wmma::fragment<wmma::matrix_b, 16, 16, 16, __half, wmma::col_major> bf;
            wmma::load_matrix_sync(bf, waS + (wn * 64 + ni * 16) * KP + k4 * 16, KP);
            wmma::mma_sync(acc[0][ni], af[0], bf, acc[0][ni]);
            wmma::mma_sync(acc[1][ni], af[1], bf, acc[1][ni]);
        }
    }
    __syncthreads();                               // tiles dead; reuse SMEM as staging

    float* st = stage + wid * 32 * SP;
#pragma unroll
    for (int mi = 0; mi < 2; ++mi)
#pragma unroll
        for (int ni = 0; ni < 4; ++ni)
            wmma::store_matrix_sync(st + mi * 16 * SP + ni * 16, acc[mi][ni], SP, wmma::mem_row_major);
    __syncwarp();

    int mbase = m0 + wm * 32;
    float a0x = A0s[wn * 64 + 2 * lane];
    float a0y = A0s[wn * 64 + 2 * lane + 1];
    if (!is_bs) {
        size_t nbase = (size_t)n0 + wn * 64 + 2 * lane;
#pragma unroll 4
        for (int r = 0; r < 32; ++r) {
            int m = mbase + r;
            if (m >= BT) break;                    // uniform within warp
            float f0 = st[r * SP + 2 * lane] + a0x;
            float f1 = st[r * SP + 2 * lane + 1] + a0y;
            *(__half2*)(g_A + (size_t)m * HH + nbase) = __floats2half2_rn(f0, f1);
        }
    } else {
        int col = wn * 64 + 2 * lane;
#pragma unroll 4
        for (int r = 0; r < 32; ++r) {
            int m = mbase + r;
            if (m >= BT) break;
            float f0 = st[r * SP + 2 * lane] + a0x;
            float f1 = st[r * SP + 2 * lane + 1] + a0y;
            *(float2*)(g_Bs + (size_t)m * Hn + col) = make_float2(f0, f1);
        }
    }
}

// ---------------- kernel 4 (phase 1): per-chunk Q = Phi - I and bias vector v, 2 CTAs/SM ----------------
// Per step: R = I + Q (fp16 SMEM), Q += A_t @ R (mma, fp32 regs), v = v + A_t v + b_t.
__global__ void __launch_bounds__(256, 2) chunk_kernel() {
    extern __shared__ char smraw[];
    __half* Ah0 = (__half*)smraw;                           // [128][AP]
    __half* Ah1 = Ah0 + 128 * AP;
    __half* Rh  = Ah1 + 128 * AP;                           // [128][AP]
    float*  vsm = (float*)(Rh + 128 * AP);                  // 128
    float*  psm = vsm + Hn;                                 // 4 x 128

    int tid = threadIdx.x;
    int cid = blockIdx.x;
    int b = cid / CC, c = cid - b * CC;
    int t0 = c * LL;
    int Lc = min(LL, Tn - t0);

    int wid = tid >> 5, lane = tid & 31;
    int Wr = (wid >> 1) * 32, Wc = (wid & 1) * 64;
    unsigned g = lane >> 3, lj = lane & 7;
    unsigned a_k = ((g >> 1) << 3) + lj, a_r = (g & 1) << 3;  // A-frag lane offsets
    unsigned b_k = ((g & 1) << 3) + lj, b_n = (g >> 1) << 3;  // B-frag lane offsets
    unsigned r_ = lane >> 2, c_ = lane & 3;

    unsigned AhB[2], RhB;
    AhB[0] = (unsigned)__cvta_generic_to_shared(Ah0);
    AhB[1] = (unsigned)__cvta_generic_to_shared(Ah1);
    RhB = (unsigned)__cvta_generic_to_shared(Rh);

    float acc[2][8][4];
#pragma unroll
    for (int mi = 0; mi < 2; ++mi)
#pragma unroll
        for (int ni = 0; ni < 8; ++ni)
#pragma unroll
            for (int e = 0; e < 4; ++e) acc[mi][ni][e] = 0.f;
    if (tid < Hn) vsm[tid] = 0.f;

    const __half* gsrc = g_A + (size_t)(b * Tn + t0) * HH;
    {   // prologue: load step 0 into buffer 0
        for (int u = tid; u < 2048; u += 256) {
            int m = u >> 4, seg = u & 15;
            cp_async16(Ah0 + m * AP + seg * 8, gsrc + m * 128 + seg * 8);
        }
        asm volatile("cp.async.commit_group;\n");
    }

    for (int s = 0; s < Lc; ++s) {
        if (s + 1 < Lc) {
            __half* dst = ((s + 1) & 1) ? Ah1 : Ah0;
            const __half* src = gsrc + (size_t)(s + 1) * HH;
            for (int u = tid; u < 2048; u += 256) {
                int m = u >> 4, seg = u & 15;
                cp_async16(dst + m * AP + seg * 8, src + m * 128 + seg * 8);
            }
        }
        asm volatile("cp.async.commit_group;\ncp.async.wait_group 1;\n");
        __syncthreads();                                    // A[s] ready; prev mma done

        // convert R = I + Q -> fp16 SMEM
#pragma unroll
        for (int mi = 0; mi < 2; ++mi)
#pragma unroll
            for (int ni = 0; ni < 8; ++ni) {
                int I = Wr + mi * 16 + (int)r_;
                int J = Wc + ni * 8 + 2 * (int)c_;
                float* a = acc[mi][ni];
                *(__half2*)(Rh + I * AP + J) =
                    __floats2half2_rn(a[0] + (I == J ? 1.f : 0.f), a[1] + (I == J + 1 ? 1.f : 0.f));
                int I2 = I + 8;
                *(__half2*)(Rh + I2 * AP + J) =
                    __floats2half2_rn(a[2] + (I2 == J ? 1.f : 0.f), a[3] + (I2 == J + 1 ? 1.f : 0.f));
            }
        __syncthreads();                                    // R ready

        unsigned Ab = AhB[s & 1];
        // mma: Q += A @ R
#pragma unroll
        for (int k = 0; k < 8; ++k) {
            unsigned a0, a1, a2, a3, a4, a5, a6, a7;
            unsigned aad = Ab + 2 * ((k * 16 + a_k) * AP + Wr + a_r);
            ldsm4t(a0, a1, a2, a3, aad);
            ldsm4t(a4, a5, a6, a7, aad + 32);
#pragma unroll
            for (int nt = 0; nt < 4; ++nt) {
                unsigned b0, b1, b2, b3;
                unsigned bad = RhB + 2 * ((k * 16 + b_k) * AP + Wc + nt * 16 + b_n);
                ldsm4t(b0, b1, b2, b3, bad);
                mma16816(acc[0][2 * nt],     a0, a1, a2, a3, b0, b1);
                mma16816(acc[0][2 * nt + 1], a0, a1, a2, a3, b2, b3);
                mma16816(acc[1][2 * nt],     a4, a5, a6, a7, b0, b1);
                mma16816(acc[1][2 * nt + 1], a4, a5, a6, a7, b2, b3);
            }
        }

        // v partials: (A v)
        {
            const __half* A = (s & 1) ? Ah1 : Ah0;
            int p = tid & 63, q = tid >> 6;
            float ax = 0.f, ay = 0.f;
#pragma unroll
            for (int jj = 0; jj < 32; ++jj) {
                int j = q * 32 + jj;
                float2 f = __half22float2(*(const __half2*)(A + j * AP + 2 * p));
                float vj = vsm[j];
                ax += f.x * vj; ay += f.y * vj;
            }
            psm[q * Hn + 2 * p] = ax;
            psm[q * Hn + 2 * p + 1] = ay;
        }
        float bsv = 0.f;
        if (tid < Hn) bsv = g_Bs[(size_t)(b * Tn + t0 + s) * Hn + tid];
        __syncthreads();                                    // partials done, A[s] free

        if (tid < Hn) {
            float v = vsm[tid] + bsv;
#pragma unroll
            for (int q = 0; q < 4; ++q) v += psm[q * Hn + tid];
            vsm[tid] = v;
        }
    }
    __syncthreads();

    // write Q (col-major [j*128+i]) and v
    __half* qb = g_Q + (size_t)cid * HH;
#pragma unroll
    for (int mi = 0; mi < 2; ++mi)
#pragma unroll
        for (int ni = 0; ni < 8; ++ni) {
            int I = Wr + mi * 16 + (int)r_;
            int J = Wc + ni * 8 + 2 * (int)c_;
            float* a = acc[mi][ni];
            qb[J * Hn + I]           = __float2half(a[0]);
            qb[(J + 1) * Hn + I]     = __float2half(a[1]);
            qb[J * Hn + I + 8]       = __float2half(a[2]);
            qb[(J + 1) * Hn + I + 8] = __float2half(a[3]);
        }
    if (tid < Hn) g_v[cid * Hn + tid] = vsm[tid];
}

// ---------------- kernel 5 (phase 2): sequential chunk combine per batch (36 iters) ----------------
__global__ void combine_kernel() {
    extern __shared__ char smraw[];
    __half* Qb = (__half*)smraw;                            // 2 x HH
    float* ysm = (float*)(Qb + 2 * HH);                     // 128
    float* psm = ysm + Hn;                                  // 8 x 128

    int b = blockIdx.x, tid = threadIdx.x;
    if (tid < Hn) ysm[tid] = g_y0[b * Hn + tid];

    {
        const __half* src = g_Q + (size_t)(b * CC) * HH;
        for (int u = tid; u < 2048; u += 512) cp_async16(Qb + u * 8, src + u * 8);
        asm volatile("cp.async.commit_group;\n");
    }

    for (int c = 0; c < CC; ++c) {
        int cid = b * CC + c;
        if (c + 1 < CC) {
            const __half* src = g_Q + (size_t)(cid + 1) * HH;
            __half* dst = Qb + ((c + 1) & 1) * HH;
            for (int u = tid; u < 2048; u += 512) cp_async16(dst + u * 8, src + u * 8);
        }
        asm volatile("cp.async.commit_group;\ncp.async.wait_group 1;\n");
        __syncthreads();

        if (tid < Hn) g_ystart[cid * Hn + tid] = ysm[tid];   // start state for phase 3

        const __half* Q = Qb + (c & 1) * HH;
        int p = tid & 63, q = tid >> 6;
        float ax = 0.f, ay = 0.f;
#pragma unroll
        for (int jj = 0; jj < 16; ++jj) {
            int j = q * 16 + jj;
            float2 f = __half22float2(*(const __half2*)(Q + j * Hn + 2 * p));
            float yj = ysm[j];
            ax += f.x * yj; ay += f.y * yj;
        }
        psm[q * Hn + 2 * p] = ax;
        psm[q * Hn + 2 * p + 1] = ay;
        __syncthreads();

        if (tid < Hn) {
            float y = ysm[tid] + g_v[cid * Hn + tid];
#pragma unroll
            for (int q2 = 0; q2 < 8; ++q2) y += psm[q2 * Hn + tid];
            ysm[tid] = y;
        }
        __syncthreads();
    }
}

// ---------------- kernel 6 (phase 3): parallel per-chunk scan, 3-stage, 2 CTAs/SM ----------------
__global__ void __launch_bounds__(512, 2) scan_kernel(float* __restrict__ Y) {
    extern __shared__ char smraw[];
    __half* Ab = (__half*)smraw;                                   // 3 stages x HH
    float* ysm = (float*)(smraw + 3 * HH * sizeof(__half));        // 128
    float* psm = ysm + Hn;                                         // 8 x 128

    int cid = blockIdx.x, tid = threadIdx.x;
    int b = cid / CC, c = cid - b * CC;
    int t0 = c * LL;
    int Lc = min(LL, Tn - t0);
    int p = tid & 63, q = tid >> 6;
    if (tid < Hn) ysm[tid] = g_ystart[cid * Hn + tid];

    const __half* gsrc = g_A + (size_t)(b * Tn + t0) * HH;
    for (int s = 0; s < 2; ++s) {
        if (s < Lc) {
            const __half* src = gsrc + (size_t)s * HH;
            __half* dst = Ab + (s % 3) * HH;
            for (int u = tid; u < 2048; u += 512) cp_async16(dst + u * 8, src + u * 8);
        }
        asm volatile("cp.async.commit_group;\n");
    }
    __syncthreads();

    for (int s = 0; s < Lc; ++s) {
        asm volatile("cp.async.wait_group 1;\n");
        __syncthreads();

        int t = t0 + s;
        float bs = 0.f;
        if (tid < Hn) bs = g_Bs[((size_t)(b * Tn + t)) * Hn + tid];

        const __half* A = Ab + (s % 3) * HH;
        float ax = 0.f, ay = 0.f;
#pragma unroll
        for (int jj = 0; jj < 16; ++jj) {
            int j = q * 16 + jj;
            float2 f = __half22float2(*(const __half2*)(A + j * Hn + p * 2));
            float yj = ysm[j];
            ax += f.x * yj; ay += f.y * yj;
        }
        *reinterpret_cast<float2*>(psm + q * Hn + 2 * p) = make_float2(ax, ay);
        __syncthreads();

        int sn = s + 2;
        if (sn < Lc) {
            const __half* src = gsrc + (size_t)sn * HH;
            __half* dst = Ab + (sn % 3) * HH;
            for (int u = tid; u < 2048; u += 512) cp_async16(dst + u * 8, src + u * 8);
        }
        asm volatile("cp.async.commit_group;\n");

        if (tid < Hn) {
            float y = ysm[tid] + bs;
#pragma unroll
            for (int qq = 0; qq < 8; ++qq) y += psm[qq * Hn + tid];
            Y[((size_t)b * Sn + t + 1) * Hn + tid] = y;
            ysm[tid] = y;
        }
    }
}

// ---------------- launcher ----------------
extern "C" void kernel_launch(void* const* d_in, const int* in_sizes, int n_in,
                              void* d_out, int out_size) {
    const float* X  = (const float*)d_in[0];
    const float* Wi = (const float*)d_in[1];
    const float* bi = (const float*)d_in[2];
    const float* Wa = (const float*)d_in[3];
    const float* Wb = (const float*)d_in[4];
    float* Y = (float*)d_out;

    const int gemm_smem  = 4 * 32 * SP * 4 + 512;                    // 35328
    const int chunk_smem = 3 * 128 * AP * 2 + (Hn + 4 * Hn) * 4;     // 107008
    const int comb_smem  = 2 * HH * 2 + (Hn + 8 * Hn) * 4;           // 70144
    const int scan_smem  = 3 * HH * 2 + (Hn + 8 * Hn) * 4;           // 102912
    cudaFuncSetAttribute(a_gemm_wmma,  cudaFuncAttributeMaxDynamicSharedMemorySize, gemm_smem);
    cudaFuncSetAttribute(chunk_kernel, cudaFuncAttributeMaxDynamicSharedMemorySize, chunk_smem);
    cudaFuncSetAttribute(combine_kernel, cudaFuncAttributeMaxDynamicSharedMemorySize, comb_smem);
    cudaFuncSetAttribute(scan_kernel,  cudaFuncAttributeMaxDynamicSharedMemorySize, scan_smem);

    wap2_kernel<<<(NW * 64 + 255) / 256, 256>>>(Wa, Wb);
    xh_kernel<<<(Bn * Sn * Dn + 255) / 256, 256>>>(X);
    y0_kernel<<<Bn, Hn>>>(X, Wi, bi, Y);
    a_gemm_wmma<<<dim3(NW / 128, BT / MB + 1), 128, gemm_smem>>>();
    chunk_kernel<<<NCHUNK, 256, chunk_smem>>>();
    combine_kernel<<<Bn, 512, comb_smem>>>();
    scan_kernel<<<NCHUNK, 512, scan_smem>>>(Y);
}

// round 16
// speedup vs baseline: 1.0933x; 1.0933x over previous
#include <cuda_runtime.h>
#include <cuda_fp16.h>

#define Bn 8
#define Sn 2048
#define Dn 64
#define Hn 128
#define Tn 2047                   // S-1 sequential steps
#define BT (Bn*Tn)                // 16376 (b,t) rows
#define HH (Hn*Hn)                // 16384
#define NW 16512                  // HH + 128 (A columns + Bs columns)
#define Kd 65                     // D+1
#define KP 72                     // half pitch for GEMM tiles
#define PH 136                    // half pitch for GEMM fp16 staging
#define CC 36                     // chunks per batch chain
#define LL 57                     // steps per chunk (35*57=1995, last=52)
#define NCHUNK (Bn*CC)            // 288 chunk CTAs
#define AP 136                    // half pitch for phase-1 A/R tiles

// ---------------- scratch (device globals: allocation-free rule) ----------------
__device__ __align__(128) __half g_A[(size_t)BT * HH];     // 536.6 MB, A[bt][j*128+i] = A_t[i][j]
__device__ __align__(128) __half g_WaPh[NW * 64];          // permuted Wa cols 1..64 (+ Wb rows), fp16
__device__ __align__(128) __half g_Xh[Bn * Sn * Dn];       // X * dt, fp16
__device__ __align__(128) __half g_Q[(size_t)NCHUNK * HH]; // chunk transition Q = Phi - I, [j*128+i]
__device__ float g_A0[NW];                                  // dt * W[:,0] constant column term
__device__ float g_Bs[(size_t)BT * Hn];                     // per-step bias
__device__ float g_v[NCHUNK * Hn];                          // chunk bias accumulation
__device__ float g_ystart[NCHUNK * Hn];                     // chunk-start states
__device__ float g_y0[Bn * Hn];

// ---------------- helpers ----------------
__device__ __forceinline__ void cp_async16(void* d, const void* s) {
    unsigned ds = (unsigned)__cvta_generic_to_shared(d);
    asm volatile("cp.async.cg.shared.global [%0], [%1], 16;\n" :: "r"(ds), "l"(s));
}
__device__ __forceinline__ void ldsm4(unsigned& r0, unsigned& r1, unsigned& r2, unsigned& r3, unsigned addr) {
    asm volatile("ldmatrix.sync.aligned.m8n8.x4.shared.b16 {%0,%1,%2,%3}, [%4];\n"
        : "=r"(r0), "=r"(r1), "=r"(r2), "=r"(r3) : "r"(addr));
}
__device__ __forceinline__ void ldsm4t(unsigned& r0, unsigned& r1, unsigned& r2, unsigned& r3, unsigned addr) {
    asm volatile("ldmatrix.sync.aligned.m8n8.x4.trans.shared.b16 {%0,%1,%2,%3}, [%4];\n"
        : "=r"(r0), "=r"(r1), "=r"(r2), "=r"(r3) : "r"(addr));
}
__device__ __forceinline__ void mma16816(float* c, unsigned a0, unsigned a1, unsigned a2, unsigned a3,
                                         unsigned b0, unsigned b1) {
    asm volatile("mma.sync.aligned.m16n8k16.row.col.f32.f16.f16.f32 "
        "{%0,%1,%2,%3}, {%4,%5,%6,%7}, {%8,%9}, {%0,%1,%2,%3};\n"
        : "+f"(c[0]), "+f"(c[1]), "+f"(c[2]), "+f"(c[3])
        : "r"(a0), "r"(a1), "r"(a2), "r"(a3), "r"(b0), "r"(b1));
}

// ---------------- kernel 0a: permute Wa (+append Wb) -> fp16, plus constant column term ----------------
__global__ void wap2_kernel(const float* __restrict__ Wa, const float* __restrict__ Wb) {
    int idx = blockIdx.x * 256 + threadIdx.x;
    const float dt = (float)(1.0 / 2047.0);
    if (idx < NW * 64) {
        int c = idx >> 6, k = idx & 63;
        if (c < HH) {
            int r = (c & 127) * Hn + (c >> 7);
            g_WaPh[idx] = __float2half(Wa[r * Kd + k + 1]);
            if (k == 0) g_A0[c] = dt * Wa[r * Kd];
        } else {
            int i = c - HH;
            g_WaPh[idx] = __float2half(Wb[i * Kd + k + 1]);
            if (k == 0) g_A0[c] = dt * Wb[i * Kd];
        }
    }
}

// ---------------- kernel 0b: X*dt -> fp16 ----------------
__global__ void xh_kernel(const float* __restrict__ X) {
    int i = blockIdx.x * 256 + threadIdx.x;
    const float dt = (float)(1.0 / 2047.0);
    if (i < Bn * Sn * Dn) g_Xh[i] = __float2half(X[i] * dt);
}

// ---------------- kernel 1: y0 = X[:,0] @ Wi.T + bi ----------------
__global__ void y0_kernel(const float* __restrict__ X, const float* __restrict__ Wi,
                          const float* __restrict__ bi, float* __restrict__ Y) {
    __shared__ float xs[Dn];
    int b = blockIdx.x, i = threadIdx.x;
    if (i < Dn) xs[i] = X[(size_t)b * Sn * Dn + i];
    __syncthreads();
    float acc = bi[i];
#pragma unroll
    for (int d = 0; d < Dn; ++d) acc += xs[d] * Wi[i * Dn + d];
    g_y0[b * Hn + i] = acc;
    Y[(size_t)b * Sn * Hn + i] = acc;   // ys[:,0]
}

// ---------------- kernel 3: A-GEMM, raw mma + fp16 register epilogue, fused Bs n-tile ----------------
// D[m][c'] = sum_k inp[m][k] * WaPh[c'][k] (+ A0). Staging in fp16 halves L1 traffic.
__global__ void __launch_bounds__(256, 2) a_gemm_mma() {
    extern __shared__ char smraw[];
    __half* inpS = (__half*)smraw;                 // [128][KP] (load phase)
    __half* waS  = inpS + 128 * KP;                // [128][KP] (load phase)
    __half* stH  = (__half*)smraw;                 // reuse after MMA: [128][PH] fp16 staging

    int tid = threadIdx.x, wid = tid >> 5, lane = tid & 31;
    int m0 = blockIdx.y * 128, n0 = blockIdx.x * 128;
    bool is_bs = (n0 >= HH);

    for (int idx = tid; idx < 128 * 8; idx += 256) {
        int r = idx >> 3, ch = idx & 7;
        int m = m0 + r;
        if (m < BT) {
            int b = m / Tn, t = m - b * Tn + 1;
            cp_async16(inpS + r * KP + ch * 8, g_Xh + ((size_t)(b * Sn + t)) * Dn + ch * 8);
        } else {
            *(uint4*)(inpS + r * KP + ch * 8) = make_uint4(0, 0, 0, 0);
        }
    }
    for (int idx = tid; idx < 128 * 8; idx += 256) {
        int r = idx >> 3, ch = idx & 7;
        cp_async16(waS + r * KP + ch * 8, g_WaPh + (size_t)(n0 + r) * 64 + ch * 8);
    }

    int Wr = (wid >> 1) * 32, Wc = (wid & 1) * 64;
    unsigned r_ = lane >> 2, c_ = lane & 3;

    // A0 column constants into registers (L2-resident broadcast)
    float a0r[8][2];
#pragma unroll
    for (int ni = 0; ni < 8; ++ni) {
        float2 t = *(const float2*)(g_A0 + n0 + Wc + ni * 8 + 2 * c_);
        a0r[ni][0] = t.x; a0r[ni][1] = t.y;
    }

    asm volatile("cp.async.commit_group;\ncp.async.wait_group 0;\n");
    __syncthreads();

    unsigned inpB = (unsigned)__cvta_generic_to_shared(inpS);
    unsigned waB  = (unsigned)__cvta_generic_to_shared(waS);

    float acc[2][8][4];
#pragma unroll
    for (int mi = 0; mi < 2; ++mi)
#pragma unroll
        for (int ni = 0; ni < 8; ++ni)
#pragma unroll
            for (int e = 0; e < 4; ++e) acc[mi][ni][e] = 0.f;

#pragma unroll
    for (int k = 0; k < 4; ++k) {
        unsigned a0, a1, a2, a3, a4, a5, a6, a7;
        unsigned aad = inpB + 2 * ((Wr + (lane & 15)) * KP + k * 16 + ((lane >> 4) << 3));
        ldsm4(a0, a1, a2, a3, aad);
        ldsm4(a4, a5, a6, a7, aad + 2 * 16 * KP);
#pragma unroll
        for (int nt = 0; nt < 4; ++nt) {
            unsigned b0, b1, b2, b3;
            unsigned bad = waB + 2 * ((Wc + nt * 16 + ((lane >> 4) << 3) + (lane & 7)) * KP
                                      + k * 16 + (((lane >> 3) & 1) << 3));
            ldsm4(b0, b1, b2, b3, bad);
            mma16816(acc[0][2 * nt],     a0, a1, a2, a3, b0, b1);
            mma16816(acc[0][2 * nt + 1], a0, a1, a2, a3, b2, b3);
            mma16816(acc[1][2 * nt],     a4, a5, a6, a7, b0, b1);
            mma16816(acc[1][2 * nt + 1], a4, a5, a6, a7, b2, b3);
        }
    }
    __syncthreads();                               // tiles dead

    if (!is_bs) {
        // convert + A0 in regs -> fp16 staging (conflict-free at pitch 136)
#pragma unroll
        for (int mi = 0; mi < 2; ++mi)
#pragma unroll
            for (int ni = 0; ni < 8; ++ni) {
                int I = Wr + mi * 16 + (int)r_;
                int J = Wc + ni * 8 + 2 * (int)c_;
                float* a = acc[mi][ni];
                *(__half2*)(stH + I * PH + J) =
                    __floats2half2_rn(a[0] + a0r[ni][0], a[1] + a0r[ni][1]);
                *(__half2*)(stH + (I + 8) * PH + J) =
                    __floats2half2_rn(a[2] + a0r[ni][0], a[3] + a0r[ni][1]);
            }
        __syncthreads();
        // coalesced uint4 sweep to global
        int seg = tid & 15, rb = tid >> 4;
#pragma unroll
        for (int it = 0; it < 8; ++it) {
            int ml = rb + it * 16;
            int m = m0 + ml;
            if (m < BT)
                *(uint4*)(g_A + (size_t)m * HH + n0 + seg * 8) = *(uint4*)(stH + ml * PH + seg * 8);
        }
    } else {
        // Bs tile: fp32 direct from registers (0.8% of CTAs)
#pragma unroll
        for (int mi = 0; mi < 2; ++mi)
#pragma unroll
            for (int ni = 0; ni < 8; ++ni) {
                int I = Wr + mi * 16 + (int)r_;
                int J = Wc + ni * 8 + 2 * (int)c_;
                float* a = acc[mi][ni];
                int m1 = m0 + I, m2 = m0 + I + 8;
                if (m1 < BT) *(float2*)(g_Bs + (size_t)m1 * Hn + J) =
                    make_float2(a[0] + a0r[ni][0], a[1] + a0r[ni][1]);
                if (m2 < BT) *(float2*)(g_Bs + (size_t)m2 * Hn + J) =
                    make_float2(a[2] + a0r[ni][0], a[3] + a0r[ni][1]);
            }
    }
}

// ---------------- kernel 4 (phase 1): per-chunk Q = Phi - I and bias vector v, 2 CTAs/SM ----------------
// Per step: R = I + Q (fp16 SMEM), Q += A_t @ R (mma, fp32 regs), v = v + A_t v + b_t.
__global__ void __launch_bounds__(256, 2) chunk_kernel() {
    extern __shared__ char smraw[];
    __half* Ah0 = (__half*)smraw;                           // [128][AP]
    __half* Ah1 = Ah0 + 128 * AP;
    __half* Rh  = Ah1 + 128 * AP;                           // [128][AP]
    float*  vsm = (float*)(Rh + 128 * AP);                  // 128
    float*  psm = vsm + Hn;                                 // 4 x 128

    int tid = threadIdx.x;
    int cid = blockIdx.x;
    int b = cid / CC, c = cid - b * CC;
    int t0 = c * LL;
    int Lc = min(LL, Tn - t0);

    int wid = tid >> 5, lane = tid & 31;
    int Wr = (wid >> 1) * 32, Wc = (wid & 1) * 64;
    unsigned g = lane >> 3, lj = lane & 7;
    unsigned a_k = ((g >> 1) << 3) + lj, a_r = (g & 1) << 3;  // A-frag lane offsets
    unsigned b_k = ((g & 1) << 3) + lj, b_n = (g >> 1) << 3;  // B-frag lane offsets
    unsigned r_ = lane >> 2, c_ = lane & 3;

    unsigned AhB[2], RhB;
    AhB[0] = (unsigned)__cvta_generic_to_shared(Ah0);
    AhB[1] = (unsigned)__cvta_generic_to_shared(Ah1);
    RhB = (unsigned)__cvta_generic_to_shared(Rh);

    float acc[2][8][4];
#pragma unroll
    for (int mi = 0; mi < 2; ++mi)
#pragma unroll
        for (int ni = 0; ni < 8; ++ni)
#pragma unroll
            for (int e = 0; e < 4; ++e) acc[mi][ni][e] = 0.f;
    if (tid < Hn) vsm[tid] = 0.f;

    const __half* gsrc = g_A + (size_t)(b * Tn + t0) * HH;
    {   // prologue: load step 0 into buffer 0
        for (int u = tid; u < 2048; u += 256) {
            int m = u >> 4, seg = u & 15;
            cp_async16(Ah0 + m * AP + seg * 8, gsrc + m * 128 + seg * 8);
        }
        asm volatile("cp.async.commit_group;\n");
    }

    for (int s = 0; s < Lc; ++s) {
        if (s + 1 < Lc) {
            __half* dst = ((s + 1) & 1) ? Ah1 : Ah0;
            const __half* src = gsrc + (size_t)(s + 1) * HH;
            for (int u = tid; u < 2048; u += 256) {
                int m = u >> 4, seg = u & 15;
                cp_async16(dst + m * AP + seg * 8, src + m * 128 + seg * 8);
            }
        }
        asm volatile("cp.async.commit_group;\ncp.async.wait_group 1;\n");
        __syncthreads();                                    // A[s] ready; prev mma done

        // convert R = I + Q -> fp16 SMEM
#pragma unroll
        for (int mi = 0; mi < 2; ++mi)
#pragma unroll
            for (int ni = 0; ni < 8; ++ni) {
                int I = Wr + mi * 16 + (int)r_;
                int J = Wc + ni * 8 + 2 * (int)c_;
                float* a = acc[mi][ni];
                *(__half2*)(Rh + I * AP + J) =
                    __floats2half2_rn(a[0] + (I == J ? 1.f : 0.f), a[1] + (I == J + 1 ? 1.f : 0.f));
                int I2 = I + 8;
                *(__half2*)(Rh + I2 * AP + J) =
                    __floats2half2_rn(a[2] + (I2 == J ? 1.f : 0.f), a[3] + (I2 == J + 1 ? 1.f : 0.f));
            }
        __syncthreads();                                    // R ready

        unsigned Ab = AhB[s & 1];
        // mma: Q += A @ R
#pragma unroll
        for (int k = 0; k < 8; ++k) {
            unsigned a0, a1, a2, a3, a4, a5, a6, a7;
            unsigned aad = Ab + 2 * ((k * 16 + a_k) * AP + Wr + a_r);
            ldsm4t(a0, a1, a2, a3, aad);
            ldsm4t(a4, a5, a6, a7, aad + 32);
#pragma unroll
            for (int nt = 0; nt < 4; ++nt) {
                unsigned b0, b1, b2, b3;
                unsigned bad = RhB + 2 * ((k * 16 + b_k) * AP + Wc + nt * 16 + b_n);
                ldsm4t(b0, b1, b2, b3, bad);
                mma16816(acc[0][2 * nt],     a0, a1, a2, a3, b0, b1);
                mma16816(acc[0][2 * nt + 1], a0, a1, a2, a3, b2, b3);
                mma16816(acc[1][2 * nt],     a4, a5, a6, a7, b0, b1);
                mma16816(acc[1][2 * nt + 1], a4, a5, a6, a7, b2, b3);
            }
        }

        // v partials: (A v)
        {
            const __half* A = (s & 1) ? Ah1 : Ah0;
            int p = tid & 63, q = tid >> 6;
            float ax = 0.f, ay = 0.f;
#pragma unroll
            for (int jj = 0; jj < 32; ++jj) {
                int j = q * 32 + jj;
                float2 f = __half22float2(*(const __half2*)(A + j * AP + 2 * p));
                float vj = vsm[j];
                ax += f.x * vj; ay += f.y * vj;
            }
            psm[q * Hn + 2 * p] = ax;
            psm[q * Hn + 2 * p + 1] = ay;
        }
        float bsv = 0.f;
        if (tid < Hn) bsv = g_Bs[(size_t)(b * Tn + t0 + s) * Hn + tid];
        __syncthreads();                                    // partials done, A[s] free

        if (tid < Hn) {
            float v = vsm[tid] + bsv;
#pragma unroll
            for (int q = 0; q < 4; ++q) v += psm[q * Hn + tid];
            vsm[tid] = v;
        }
    }
    __syncthreads();

    // write Q (col-major [j*128+i]) and v
    __half* qb = g_Q + (size_t)cid * HH;
#pragma unroll
    for (int mi = 0; mi < 2; ++mi)
#pragma unroll
        for (int ni = 0; ni < 8; ++ni) {
            int I = Wr + mi * 16 + (int)r_;
            int J = Wc + ni * 8 + 2 * (int)c_;
            float* a = acc[mi][ni];
            qb[J * Hn + I]           = __float2half(a[0]);
            qb[(J + 1) * Hn + I]     = __float2half(a[1]);
            qb[J * Hn + I + 8]       = __float2half(a[2]);
            qb[(J + 1) * Hn + I + 8] = __float2half(a[3]);
        }
    if (tid < Hn) g_v[cid * Hn + tid] = vsm[tid];
}

// ---------------- kernel 5 (phase 2): sequential chunk combine per batch (36 iters) ----------------
__global__ void combine_kernel() {
    extern __shared__ char smraw[];
    __half* Qb = (__half*)smraw;                            // 2 x HH
    float* ysm = (float*)(Qb + 2 * HH);                     // 128
    float* psm = ysm + Hn;                                  // 8 x 128

    int b = blockIdx.x, tid = threadIdx.x;
    if (tid < Hn) ysm[tid] = g_y0[b * Hn + tid];

    {
        const __half* src = g_Q + (size_t)(b * CC) * HH;
        for (int u = tid; u < 2048; u += 512) cp_async16(Qb + u * 8, src + u * 8);
        asm volatile("cp.async.commit_group;\n");
    }

    for (int c = 0; c < CC; ++c) {
        int cid = b * CC + c;
        if (c + 1 < CC) {
            const __half* src = g_Q + (size_t)(cid + 1) * HH;
            __half* dst = Qb + ((c + 1) & 1) * HH;
            for (int u = tid; u < 2048; u += 512) cp_async16(dst + u * 8, src + u * 8);
        }
        asm volatile("cp.async.commit_group;\ncp.async.wait_group 1;\n");
        __syncthreads();

        if (tid < Hn) g_ystart[cid * Hn + tid] = ysm[tid];   // start state for phase 3

        const __half* Q = Qb + (c & 1) * HH;
        int p = tid & 63, q = tid >> 6;
        float ax = 0.f, ay = 0.f;
#pragma unroll
        for (int jj = 0; jj < 16; ++jj) {
            int j = q * 16 + jj;
            float2 f = __half22float2(*(const __half2*)(Q + j * Hn + 2 * p));
            float yj = ysm[j];
            ax += f.x * yj; ay += f.y * yj;
        }
        psm[q * Hn + 2 * p] = ax;
        psm[q * Hn + 2 * p + 1] = ay;
        __syncthreads();

        if (tid < Hn) {
            float y = ysm[tid] + g_v[cid * Hn + tid];
#pragma unroll
            for (int q2 = 0; q2 < 8; ++q2) y += psm[q2 * Hn + tid];
            ysm[tid] = y;
        }
        __syncthreads();
    }
}

// ---------------- kernel 6 (phase 3): parallel per-chunk scan, 3-stage, 2 CTAs/SM ----------------
__global__ void __launch_bounds__(512, 2) scan_kernel(float* __restrict__ Y) {
    extern __shared__ char smraw[];
    __half* Ab = (__half*)smraw;                                   // 3 stages x HH
    float* ysm = (float*)(smraw + 3 * HH * sizeof(__half));        // 128
    float* psm = ysm + Hn;                                         // 8 x 128

    int cid = blockIdx.x, tid = threadIdx.x;
    int b = cid / CC, c = cid - b * CC;
    int t0 = c * LL;
    int Lc = min(LL, Tn - t0);
    int p = tid & 63, q = tid >> 6;
    if (tid < Hn) ysm[tid] = g_ystart[cid * Hn + tid];

    const __half* gsrc = g_A + (size_t)(b * Tn + t0) * HH;
    for (int s = 0; s < 2; ++s) {
        if (s < Lc) {
            const __half* src = gsrc + (size_t)s * HH;
            __half* dst = Ab + (s % 3) * HH;
            for (int u = tid; u < 2048; u += 512) cp_async16(dst + u * 8, src + u * 8);
        }
        asm volatile("cp.async.commit_group;\n");
    }
    __syncthreads();

    for (int s = 0; s < Lc; ++s) {
        asm volatile("cp.async.wait_group 1;\n");
        __syncthreads();

        int t = t0 + s;
        float bs = 0.f;
        if (tid < Hn) bs = g_Bs[((size_t)(b * Tn + t)) * Hn + tid];

        const __half* A = Ab + (s % 3) * HH;
        float ax = 0.f, ay = 0.f;
#pragma unroll
        for (int jj = 0; jj < 16; ++jj) {
            int j = q * 16 + jj;
            float2 f = __half22float2(*(const __half2*)(A + j * Hn + p * 2));
            float yj = ysm[j];
            ax += f.x * yj; ay += f.y * yj;
        }
        *reinterpret_cast<float2*>(psm + q * Hn + 2 * p) = make_float2(ax, ay);
        __syncthreads();

        int sn = s + 2;
        if (sn < Lc) {
            const __half* src = gsrc + (size_t)sn * HH;
            __half* dst = Ab + (sn % 3) * HH;
            for (int u = tid; u < 2048; u += 512) cp_async16(dst + u * 8, src + u * 8);
        }
        asm volatile("cp.async.commit_group;\n");

        if (tid < Hn) {
            float y = ysm[tid] + bs;
#pragma unroll
            for (int qq = 0; qq < 8; ++qq) y += psm[qq * Hn + tid];
            Y[((size_t)b * Sn + t + 1) * Hn + tid] = y;
            ysm[tid] = y;
        }
    }
}

// ---------------- launcher ----------------
extern "C" void kernel_launch(void* const* d_in, const int* in_sizes, int n_in,
                              void* d_out, int out_size) {
    const float* X  = (const float*)d_in[0];
    const float* Wi = (const float*)d_in[1];
    const float* bi = (const float*)d_in[2];
    const float* Wa = (const float*)d_in[3];
    const float* Wb = (const float*)d_in[4];
    float* Y = (float*)d_out;

    const int gemm_smem  = 2 * 128 * KP * 2;                         // 36864 (>= 128*PH*2 staging)
    const int chunk_smem = 3 * 128 * AP * 2 + (Hn + 4 * Hn) * 4;     // 107008
    const int comb_smem  = 2 * HH * 2 + (Hn + 8 * Hn) * 4;           // 70144
    const int scan_smem  = 3 * HH * 2 + (Hn + 8 * Hn) * 4;           // 102912
    cudaFuncSetAttribute(a_gemm_mma,   cudaFuncAttributeMaxDynamicSharedMemorySize, gemm_smem);
    cudaFuncSetAttribute(chunk_kernel, cudaFuncAttributeMaxDynamicSharedMemorySize, chunk_smem);
    cudaFuncSetAttribute(combine_kernel, cudaFuncAttributeMaxDynamicSharedMemorySize, comb_smem);
    cudaFuncSetAttribute(scan_kernel,  cudaFuncAttributeMaxDynamicSharedMemorySize, scan_smem);

    wap2_kernel<<<(NW * 64 + 255) / 256, 256>>>(Wa, Wb);
    xh_kernel<<<(Bn * Sn * Dn + 255) / 256, 256>>>(X);
    y0_kernel<<<Bn, Hn>>>(X, Wi, bi, Y);
    a_gemm_mma<<<dim3(NW / 128, 128), 256, gemm_smem>>>();
    chunk_kernel<<<NCHUNK, 256, chunk_smem>>>();
    combine_kernel<<<Bn, 512, comb_smem>>>();
    scan_kernel<<<NCHUNK, 512, scan_smem>>>(Y);
}

// round 17
// speedup vs baseline: 1.1560x; 1.0573x over previous
#include <cuda_runtime.h>
#include <cuda_fp16.h>

#define Bn 8
#define Sn 2048
#define Dn 64
#define Hn 128
#define Tn 2047                   // S-1 sequential steps
#define BT (Bn*Tn)                // 16376 (b,t) rows
#define HH (Hn*Hn)                // 16384
#define NW 16512                  // HH + 128 (A columns + Bs columns)
#define Kd 65                     // D+1
#define KP 72                     // half pitch for GEMM tiles
#define PH 136                    // half pitch for GEMM fp16 staging
#define MG 4                      // m-subtiles per persistent GEMM CTA
#define CC 36                     // chunks per batch chain
#define LL 57                     // steps per chunk (35*57=1995, last=52)
#define NCHUNK (Bn*CC)            // 288 chunk CTAs
#define AP 136                    // half pitch for phase-1 A/R tiles

// ---------------- scratch (device globals: allocation-free rule) ----------------
__device__ __align__(128) __half g_A[(size_t)BT * HH];     // 536.6 MB, A[bt][j*128+i] = A_t[i][j]
__device__ __align__(128) __half g_WaPh[NW * 64];          // permuted Wa cols 1..64 (+ Wb rows), fp16
__device__ __align__(128) __half g_Xh[Bn * Sn * Dn];       // X * dt, fp16
__device__ __align__(128) __half g_Q[(size_t)NCHUNK * HH]; // chunk transition Q = Phi - I, [j*128+i]
__device__ float g_A0[NW];                                  // dt * W[:,0] constant column term
__device__ float g_Bs[(size_t)BT * Hn];                     // per-step bias
__device__ float g_v[NCHUNK * Hn];                          // chunk bias accumulation
__device__ float g_ystart[NCHUNK * Hn];                     // chunk-start states
__device__ float g_y0[Bn * Hn];

// ---------------- helpers ----------------
__device__ __forceinline__ void cp_async16(void* d, const void* s) {
    unsigned ds = (unsigned)__cvta_generic_to_shared(d);
    asm volatile("cp.async.cg.shared.global [%0], [%1], 16;\n" :: "r"(ds), "l"(s));
}
__device__ __forceinline__ void ldsm4(unsigned& r0, unsigned& r1, unsigned& r2, unsigned& r3, unsigned addr) {
    asm volatile("ldmatrix.sync.aligned.m8n8.x4.shared.b16 {%0,%1,%2,%3}, [%4];\n"
        : "=r"(r0), "=r"(r1), "=r"(r2), "=r"(r3) : "r"(addr));
}
__device__ __forceinline__ void ldsm4t(unsigned& r0, unsigned& r1, unsigned& r2, unsigned& r3, unsigned addr) {
    asm volatile("ldmatrix.sync.aligned.m8n8.x4.trans.shared.b16 {%0,%1,%2,%3}, [%4];\n"
        : "=r"(r0), "=r"(r1), "=r"(r2), "=r"(r3) : "r"(addr));
}
__device__ __forceinline__ void ldsm2t(unsigned& r0, unsigned& r1, unsigned addr) {
    asm volatile("ldmatrix.sync.aligned.m8n8.x2.trans.shared.b16 {%0,%1}, [%2];\n"
        : "=r"(r0), "=r"(r1) : "r"(addr));
}
__device__ __forceinline__ void mma16816(float* c, unsigned a0, unsigned a1, unsigned a2, unsigned a3,
                                         unsigned b0, unsigned b1) {
    asm volatile("mma.sync.aligned.m16n8k16.row.col.f32.f16.f16.f32 "
        "{%0,%1,%2,%3}, {%4,%5,%6,%7}, {%8,%9}, {%0,%1,%2,%3};\n"
        : "+f"(c[0]), "+f"(c[1]), "+f"(c[2]), "+f"(c[3])
        : "r"(a0), "r"(a1), "r"(a2), "r"(a3), "r"(b0), "r"(b1));
}

// ---------------- kernel 0a: permute Wa (+append Wb) -> fp16, plus constant column term ----------------
__global__ void wap2_kernel(const float* __restrict__ Wa, const float* __restrict__ Wb) {
    int idx = blockIdx.x * 256 + threadIdx.x;
    const float dt = (float)(1.0 / 2047.0);
    if (idx < NW * 64) {
        int c = idx >> 6, k = idx & 63;
        if (c < HH) {
            int r = (c & 127) * Hn + (c >> 7);
            g_WaPh[idx] = __float2half(Wa[r * Kd + k + 1]);
            if (k == 0) g_A0[c] = dt * Wa[r * Kd];
        } else {
            int i = c - HH;
            g_WaPh[idx] = __float2half(Wb[i * Kd + k + 1]);
            if (k == 0) g_A0[c] = dt * Wb[i * Kd];
        }
    }
}

// ---------------- kernel 0b: X*dt -> fp16 ----------------
__global__ void xh_kernel(const float* __restrict__ X) {
    int i = blockIdx.x * 256 + threadIdx.x;
    const float dt = (float)(1.0 / 2047.0);
    if (i < Bn * Sn * Dn) g_Xh[i] = __float2half(X[i] * dt);
}

// ---------------- kernel 1: y0 = X[:,0] @ Wi.T + bi ----------------
__global__ void y0_kernel(const float* __restrict__ X, const float* __restrict__ Wi,
                          const float* __restrict__ bi, float* __restrict__ Y) {
    __shared__ float xs[Dn];
    int b = blockIdx.x, i = threadIdx.x;
    if (i < Dn) xs[i] = X[(size_t)b * Sn * Dn + i];
    __syncthreads();
    float acc = bi[i];
#pragma unroll
    for (int d = 0; d < Dn; ++d) acc += xs[d] * Wi[i * Dn + d];
    g_y0[b * Hn + i] = acc;
    Y[(size_t)b * Sn * Hn + i] = acc;   // ys[:,0]
}

// ---------------- kernel 3: persistent A-GEMM, raw mma, fp16 staging, prefetched m-subtiles ----------------
// W tile stays resident; MG m-subtiles stream through double-buffered inp with cp.async overlap.
__global__ void __launch_bounds__(256, 2) a_gemm_mma() {
    extern __shared__ char smraw[];
    __half* waS   = (__half*)smraw;                // [128][KP] persistent
    __half* inpS0 = waS + 128 * KP;                // [128][KP] double buffer
    __half* inpS1 = inpS0 + 128 * KP;
    __half* stH   = inpS1 + 128 * KP;              // [128][PH] fp16 staging

    int tid = threadIdx.x, wid = tid >> 5, lane = tid & 31;
    int n0 = blockIdx.x * 128;
    int mg0 = blockIdx.y * (128 * MG);
    bool is_bs = (n0 >= HH);

    int Wr = (wid >> 1) * 32, Wc = (wid & 1) * 64;
    unsigned r_ = lane >> 2, c_ = lane & 3;

    // A0 column constants (L2-resident broadcast)
    float a0r[8][2];
#pragma unroll
    for (int ni = 0; ni < 8; ++ni) {
        float2 t = *(const float2*)(g_A0 + n0 + Wc + ni * 8 + 2 * c_);
        a0r[ni][0] = t.x; a0r[ni][1] = t.y;
    }

    // prologue: W tile + inp subtile 0 (one group)
    for (int idx = tid; idx < 128 * 8; idx += 256) {
        int r = idx >> 3, ch = idx & 7;
        cp_async16(waS + r * KP + ch * 8, g_WaPh + (size_t)(n0 + r) * 64 + ch * 8);
    }
    for (int idx = tid; idx < 128 * 8; idx += 256) {
        int r = idx >> 3, ch = idx & 7;
        int m = mg0 + r;
        if (m < BT) {
            int b = m / Tn, t = m - b * Tn + 1;
            cp_async16(inpS0 + r * KP + ch * 8, g_Xh + ((size_t)(b * Sn + t)) * Dn + ch * 8);
        } else {
            *(uint4*)(inpS0 + r * KP + ch * 8) = make_uint4(0, 0, 0, 0);
        }
    }
    asm volatile("cp.async.commit_group;\n");

    unsigned waB = (unsigned)__cvta_generic_to_shared(waS);

    for (int st = 0; st < MG; ++st) {
        int m0 = mg0 + st * 128;
        __half* cur = (st & 1) ? inpS1 : inpS0;
        // prefetch next subtile into the other buffer
        if (st + 1 < MG) {
            __half* nxt = (st & 1) ? inpS0 : inpS1;
            int mb = mg0 + (st + 1) * 128;
            for (int idx = tid; idx < 128 * 8; idx += 256) {
                int r = idx >> 3, ch = idx & 7;
                int m = mb + r;
                if (m < BT) {
                    int b = m / Tn, t = m - b * Tn + 1;
                    cp_async16(nxt + r * KP + ch * 8, g_Xh + ((size_t)(b * Sn + t)) * Dn + ch * 8);
                } else {
                    *(uint4*)(nxt + r * KP + ch * 8) = make_uint4(0, 0, 0, 0);
                }
            }
        }
        asm volatile("cp.async.commit_group;\ncp.async.wait_group 1;\n");
        __syncthreads();                           // cur visible to all; stH free from prev sweep

        unsigned inpB = (unsigned)__cvta_generic_to_shared(cur);
        float acc[2][8][4];
#pragma unroll
        for (int mi = 0; mi < 2; ++mi)
#pragma unroll
            for (int ni = 0; ni < 8; ++ni)
#pragma unroll
                for (int e = 0; e < 4; ++e) acc[mi][ni][e] = 0.f;

#pragma unroll
        for (int k = 0; k < 4; ++k) {
            unsigned a0, a1, a2, a3, a4, a5, a6, a7;
            unsigned aad = inpB + 2 * ((Wr + (lane & 15)) * KP + k * 16 + ((lane >> 4) << 3));
            ldsm4(a0, a1, a2, a3, aad);
            ldsm4(a4, a5, a6, a7, aad + 2 * 16 * KP);
#pragma unroll
            for (int nt = 0; nt < 4; ++nt) {
                unsigned b0, b1, b2, b3;
                unsigned bad = waB + 2 * ((Wc + nt * 16 + ((lane >> 4) << 3) + (lane & 7)) * KP
                                          + k * 16 + (((lane >> 3) & 1) << 3));
                ldsm4(b0, b1, b2, b3, bad);
                mma16816(acc[0][2 * nt],     a0, a1, a2, a3, b0, b1);
                mma16816(acc[0][2 * nt + 1], a0, a1, a2, a3, b2, b3);
                mma16816(acc[1][2 * nt],     a4, a5, a6, a7, b0, b1);
                mma16816(acc[1][2 * nt + 1], a4, a5, a6, a7, b2, b3);
            }
        }

        if (!is_bs) {
            // convert + A0 in regs -> fp16 staging (conflict-free at pitch 136)
#pragma unroll
            for (int mi = 0; mi < 2; ++mi)
#pragma unroll
                for (int ni = 0; ni < 8; ++ni) {
                    int I = Wr + mi * 16 + (int)r_;
                    int J = Wc + ni * 8 + 2 * (int)c_;
                    float* a = acc[mi][ni];
                    *(__half2*)(stH + I * PH + J) =
                        __floats2half2_rn(a[0] + a0r[ni][0], a[1] + a0r[ni][1]);
                    *(__half2*)(stH + (I + 8) * PH + J) =
                        __floats2half2_rn(a[2] + a0r[ni][0], a[3] + a0r[ni][1]);
                }
            __syncthreads();                       // staging complete
            int seg = tid & 15, rb = tid >> 4;
#pragma unroll
            for (int it = 0; it < 8; ++it) {
                int ml = rb + it * 16;
                int m = m0 + ml;
                if (m < BT)
                    *(uint4*)(g_A + (size_t)m * HH + n0 + seg * 8) = *(uint4*)(stH + ml * PH + seg * 8);
            }
        } else {
            // Bs tile: fp32 direct from registers (0.8% of CTAs)
#pragma unroll
            for (int mi = 0; mi < 2; ++mi)
#pragma unroll
                for (int ni = 0; ni < 8; ++ni) {
                    int I = Wr + mi * 16 + (int)r_;
                    int J = Wc + ni * 8 + 2 * (int)c_;
                    float* a = acc[mi][ni];
                    int m1 = m0 + I, m2 = m0 + I + 8;
                    if (m1 < BT) *(float2*)(g_Bs + (size_t)m1 * Hn + J) =
                        make_float2(a[0] + a0r[ni][0], a[1] + a0r[ni][1]);
                    if (m2 < BT) *(float2*)(g_Bs + (size_t)m2 * Hn + J) =
                        make_float2(a[2] + a0r[ni][0], a[3] + a0r[ni][1]);
                }
            __syncthreads();                       // keep sync structure uniform
        }
    }
}

// ---------------- kernel 4 (phase 1): per-chunk Q = Phi - I and v via augmented column ----------------
// Per step: R = [I + Q | v] (fp16 SMEM, col 128 = v); one mma pass updates Q and yields A@v.
__global__ void __launch_bounds__(256, 2) chunk_kernel() {
    extern __shared__ char smraw[];
    __half* Ah0 = (__half*)smraw;                           // [128][AP]
    __half* Ah1 = Ah0 + 128 * AP;
    __half* Rh  = Ah1 + 128 * AP;                           // [128][AP], col 128 = v
    float*  vsm = (float*)(Rh + 128 * AP);                  // 128
    float*  psm = vsm + Hn;                                 // 128 (A@v partials)

    int tid = threadIdx.x;
    int cid = blockIdx.x;
    int b = cid / CC, c = cid - b * CC;
    int t0 = c * LL;
    int Lc = min(LL, Tn - t0);

    int wid = tid >> 5, lane = tid & 31;
    int Wr = (wid >> 1) * 32, Wc = (wid & 1) * 64;
    unsigned g = lane >> 3, lj = lane & 7;
    unsigned a_k = ((g >> 1) << 3) + lj, a_r = (g & 1) << 3;  // A-frag lane offsets
    unsigned b_k = ((g & 1) << 3) + lj, b_n = (g >> 1) << 3;  // B-frag lane offsets
    unsigned r_ = lane >> 2, c_ = lane & 3;
    bool oddw = (wid & 1);

    unsigned AhB[2], RhB;
    AhB[0] = (unsigned)__cvta_generic_to_shared(Ah0);
    AhB[1] = (unsigned)__cvta_generic_to_shared(Ah1);
    RhB = (unsigned)__cvta_generic_to_shared(Rh);

    float acc[2][8][4];
    float accE[2][4];
#pragma unroll
    for (int mi = 0; mi < 2; ++mi) {
#pragma unroll
        for (int ni = 0; ni < 8; ++ni)
#pragma unroll
            for (int e = 0; e < 4; ++e) acc[mi][ni][e] = 0.f;
#pragma unroll
        for (int e = 0; e < 4; ++e) accE[mi][e] = 0.f;
    }
    if (tid < Hn) {
        vsm[tid] = 0.f;
        psm[tid] = 0.f;
#pragma unroll
        for (int j = 128; j < AP; ++j) Rh[tid * AP + j] = __float2half(0.f);
    }

    const __half* gsrc = g_A + (size_t)(b * Tn + t0) * HH;
    {   // prologue: load step 0 into buffer 0
        for (int u = tid; u < 2048; u += 256) {
            int m = u >> 4, seg = u & 15;
            cp_async16(Ah0 + m * AP + seg * 8, gsrc + m * 128 + seg * 8);
        }
        asm volatile("cp.async.commit_group;\n");
    }

    for (int s = 0; s < Lc; ++s) {
        if (s + 1 < Lc) {
            __half* dst = ((s + 1) & 1) ? Ah1 : Ah0;
            const __half* src = gsrc + (size_t)(s + 1) * HH;
            for (int u = tid; u < 2048; u += 256) {
                int m = u >> 4, seg = u & 15;
                cp_async16(dst + m * AP + seg * 8, src + m * 128 + seg * 8);
            }
        }
        asm volatile("cp.async.commit_group;\ncp.async.wait_group 1;\n");
        __syncthreads();                                    // A[s] ready; prev mma done; vsm updated

        // R = [I + Q | v] -> fp16 SMEM
#pragma unroll
        for (int mi = 0; mi < 2; ++mi)
#pragma unroll
            for (int ni = 0; ni < 8; ++ni) {
                int I = Wr + mi * 16 + (int)r_;
                int J = Wc + ni * 8 + 2 * (int)c_;
                float* a = acc[mi][ni];
                *(__half2*)(Rh + I * AP + J) =
                    __floats2half2_rn(a[0] + (I == J ? 1.f : 0.f), a[1] + (I == J + 1 ? 1.f : 0.f));
                int I2 = I + 8;
                *(__half2*)(Rh + I2 * AP + J) =
                    __floats2half2_rn(a[2] + (I2 == J ? 1.f : 0.f), a[3] + (I2 == J + 1 ? 1.f : 0.f));
            }
        if (tid < Hn) Rh[tid * AP + 128] = __float2half(vsm[tid]);
        __syncthreads();                                    // R ready

        unsigned Ab = AhB[s & 1];
        // mma: Q += A @ R ; odd warps also accE += A @ v-column
#pragma unroll
        for (int k = 0; k < 8; ++k) {
            unsigned a0, a1, a2, a3, a4, a5, a6, a7;
            unsigned aad = Ab + 2 * ((k * 16 + a_k) * AP + Wr + a_r);
            ldsm4t(a0, a1, a2, a3, aad);
            ldsm4t(a4, a5, a6, a7, aad + 32);
#pragma unroll
            for (int nt = 0; nt < 4; ++nt) {
                unsigned b0, b1, b2, b3;
                unsigned bad = RhB + 2 * ((k * 16 + b_k) * AP + Wc + nt * 16 + b_n);
                ldsm4t(b0, b1, b2, b3, bad);
                mma16816(acc[0][2 * nt],     a0, a1, a2, a3, b0, b1);
                mma16816(acc[0][2 * nt + 1], a0, a1, a2, a3, b2, b3);
                mma16816(acc[1][2 * nt],     a4, a5, a6, a7, b0, b1);
                mma16816(acc[1][2 * nt + 1], a4, a5, a6, a7, b2, b3);
            }
            if (oddw) {
                unsigned e0, e1;
                unsigned ead = RhB + 2 * ((k * 16 + (lane & 15)) * AP + 128);
                ldsm2t(e0, e1, ead);
                mma16816(accE[0], a0, a1, a2, a3, e0, e1);
                mma16816(accE[1], a4, a5, a6, a7, e0, e1);
            }
        }

        if (oddw) {
            if (c_ == 0) {
#pragma unroll
                for (int mi = 0; mi < 2; ++mi) {
                    int I = Wr + mi * 16 + (int)r_;
                    psm[I] = accE[mi][0];
                    psm[I + 8] = accE[mi][2];
                }
            }
#pragma unroll
            for (int mi = 0; mi < 2; ++mi)
#pragma unroll
                for (int e = 0; e < 4; ++e) accE[mi][e] = 0.f;
        }
        float bsv = 0.f;
        if (tid < Hn) bsv = g_Bs[(size_t)(b * Tn + t0 + s) * Hn + tid];
        __syncthreads();                                    // psm ready, mma drained

        if (tid < Hn) vsm[tid] += psm[tid] + bsv;
    }
    __syncthreads();

    // write Q (col-major [j*128+i]) and v
    __half* qb = g_Q + (size_t)cid * HH;
#pragma unroll
    for (int mi = 0; mi < 2; ++mi)
#pragma unroll
        for (int ni = 0; ni < 8; ++ni) {
            int I = Wr + mi * 16 + (int)r_;
            int J = Wc + ni * 8 + 2 * (int)c_;
            float* a = acc[mi][ni];
            qb[J * Hn + I]           = __float2half(a[0]);
            qb[(J + 1) * Hn + I]     = __float2half(a[1]);
            qb[J * Hn + I + 8]       = __float2half(a[2]);
            qb[(J + 1) * Hn + I + 8] = __float2half(a[3]);
        }
    if (tid < Hn) g_v[cid * Hn + tid] = vsm[tid];
}

// ---------------- kernel 5 (phase 2): sequential chunk combine per batch (36 iters) ----------------
__global__ void combine_kernel() {
    extern __shared__ char smraw[];
    __half* Qb = (__half*)smraw;                            // 2 x HH
    float* ysm = (float*)(Qb + 2 * HH);                     // 128
    float* psm = ysm + Hn;                                  // 8 x 128

    int b = blockIdx.x, tid = threadIdx.x;
    if (tid < Hn) ysm[tid] = g_y0[b * Hn + tid];

    {
        const __half* src = g_Q + (size_t)(b * CC) * HH;
        for (int u = tid; u < 2048; u += 512) cp_async16(Qb + u * 8, src + u * 8);
        asm volatile("cp.async.commit_group;\n");
    }

    for (int c = 0; c < CC; ++c) {
        int cid = b * CC + c;
        if (c + 1 < CC) {
            const __half* src = g_Q + (size_t)(cid + 1) * HH;
            __half* dst = Qb + ((c + 1) & 1) * HH;
            for (int u = tid; u < 2048; u += 512) cp_async16(dst + u * 8, src + u * 8);
        }
        asm volatile("cp.async.commit_group;\ncp.async.wait_group 1;\n");
        __syncthreads();

        if (tid < Hn) g_ystart[cid * Hn + tid] = ysm[tid];   // start state for phase 3

        const __half* Q = Qb + (c & 1) * HH;
        int p = tid & 63, q = tid >> 6;
        float ax = 0.f, ay = 0.f;
#pragma unroll
        for (int jj = 0; jj < 16; ++jj) {
            int j = q * 16 + jj;
            float2 f = __half22float2(*(const __half2*)(Q + j * Hn + 2 * p));
            float yj = ysm[j];
            ax += f.x * yj; ay += f.y * yj;
        }
        psm[q * Hn + 2 * p] = ax;
        psm[q * Hn + 2 * p + 1] = ay;
        __syncthreads();

        if (tid < Hn) {
            float y = ysm[tid] + g_v[cid * Hn + tid];
#pragma unroll
            for (int q2 = 0; q2 < 8; ++q2) y += psm[q2 * Hn + tid];
            ysm[tid] = y;
        }
        __syncthreads();
    }
}

// ---------------- kernel 6 (phase 3): parallel per-chunk scan, 3-stage, 2 CTAs/SM ----------------
__global__ void __launch_bounds__(512, 2) scan_kernel(float* __restrict__ Y) {
    extern __shared__ char smraw[];
    __half* Ab = (__half*)smraw;                                   // 3 stages x HH
    float* ysm = (float*)(smraw + 3 * HH * sizeof(__half));        // 128
    float* psm = ysm + Hn;                                         // 8 x 128

    int cid = blockIdx.x, tid = threadIdx.x;
    int b = cid / CC, c = cid - b * CC;
    int t0 = c * LL;
    int Lc = min(LL, Tn - t0);
    int p = tid & 63, q = tid >> 6;
    if (tid < Hn) ysm[tid] = g_ystart[cid * Hn + tid];

    const __half* gsrc = g_A + (size_t)(b * Tn + t0) * HH;
    for (int s = 0; s < 2; ++s) {
        if (s < Lc) {
            const __half* src = gsrc + (size_t)s * HH;
            __half* dst = Ab + (s % 3) * HH;
            for (int u = tid; u < 2048; u += 512) cp_async16(dst + u * 8, src + u * 8);
        }
        asm volatile("cp.async.commit_group;\n");
    }
    __syncthreads();

    for (int s = 0; s < Lc; ++s) {
        asm volatile("cp.async.wait_group 1;\n");
        __syncthreads();

        int t = t0 + s;
        float bs = 0.f;
        if (tid < Hn) bs = g_Bs[((size_t)(b * Tn + t)) * Hn + tid];

        const __half* A = Ab + (s % 3) * HH;
        float ax = 0.f, ay = 0.f;
#pragma unroll
        for (int jj = 0; jj < 16; ++jj) {
            int j = q * 16 + jj;
            float2 f = __half22float2(*(const __half2*)(A + j * Hn + p * 2));
            float yj = ysm[j];
            ax += f.x * yj; ay += f.y * yj;
        }
        *reinterpret_cast<float2*>(psm + q * Hn + 2 * p) = make_float2(ax, ay);
        __syncthreads();

        int sn = s + 2;
        if (sn < Lc) {
            const __half* src = gsrc + (size_t)sn * HH;
            __half* dst = Ab + (sn % 3) * HH;
            for (int u = tid; u < 2048; u += 512) cp_async16(dst + u * 8, src + u * 8);
        }
        asm volatile("cp.async.commit_group;\n");

        if (tid < Hn) {
            float y = ysm[tid] + bs;
#pragma unroll
            for (int qq = 0; qq < 8; ++qq) y += psm[qq * Hn + tid];
            Y[((size_t)b * Sn + t + 1) * Hn + tid] = y;
            ysm[tid] = y;
        }
    }
}

// ---------------- launcher ----------------
extern "C" void kernel_launch(void* const* d_in, const int* in_sizes, int n_in,
                              void* d_out, int out_size) {
    const float* X  = (const float*)d_in[0];
    const float* Wi = (const float*)d_in[1];
    const float* bi = (const float*)d_in[2];
    const float* Wa = (const float*)d_in[3];
    const float* Wb = (const float*)d_in[4];
    float* Y = (float*)d_out;

    const int gemm_smem  = 3 * 128 * KP * 2 + 128 * PH * 2;          // 90112
    const int chunk_smem = 3 * 128 * AP * 2 + 2 * Hn * 4;            // 105472
    const int comb_smem  = 2 * HH * 2 + (Hn + 8 * Hn) * 4;           // 70144
    const int scan_smem  = 3 * HH * 2 + (Hn + 8 * Hn) * 4;           // 102912
    cudaFuncSetAttribute(a_gemm_mma,   cudaFuncAttributeMaxDynamicSharedMemorySize, gemm_smem);
    cudaFuncSetAttribute(chunk_kernel, cudaFuncAttributeMaxDynamicSharedMemorySize, chunk_smem);
    cudaFuncSetAttribute(combine_kernel, cudaFuncAttributeMaxDynamicSharedMemorySize, comb_smem);
    cudaFuncSetAttribute(scan_kernel,  cudaFuncAttributeMaxDynamicSharedMemorySize, scan_smem);

    wap2_kernel<<<(NW * 64 + 255) / 256, 256>>>(Wa, Wb);
    xh_kernel<<<(Bn * Sn * Dn + 255) / 256, 256>>>(X);
    y0_kernel<<<Bn, Hn>>>(X, Wi, bi, Y);
    a_gemm_mma<<<dim3(NW / 128, 32), 256, gemm_smem>>>();
    chunk_kernel<<<NCHUNK, 256, chunk_smem>>>();
    combine_kernel<<<Bn, 512, comb_smem>>>();
    scan_kernel<<<NCHUNK, 512, scan_smem>>>(Y);
}